// round 17
// baseline (speedup 1.0000x reference)
#include <cuda_runtime.h>
#include <cuda_fp16.h>
#include <cstdint>

// Problem constants
#define BB 512
#define SS 512
#define CC 32
#define DD 512
#define EE 8
#define EMBW 32

// ---------------------------------------------------------------------------
// Scratch (device globals — no allocation allowed)
// ---------------------------------------------------------------------------
__device__ __half g_Ah[DD * SS];        // Wmix^T fp16  [d][s] K-major
__device__ __half g_Xh[BB * CC * SS];   // xn fp16 [n=(b,v)][s] K-major

// ---------------------------------------------------------------------------
// helpers
// ---------------------------------------------------------------------------
__device__ __forceinline__ uint32_t smem_u32(const void* p) {
    uint32_t a;
    asm("{ .reg .u64 t; cvta.to.shared.u64 t, %1; cvt.u32.u64 %0, t; }"
        : "=r"(a) : "l"(p));
    return a;
}
__device__ __forceinline__ void cp_async16(uint32_t dst_smem, const void* src) {
    asm volatile("cp.async.cg.shared.global [%0], [%1], 16;"
                 :: "r"(dst_smem), "l"(src));
}
__device__ __forceinline__ void ldsm4(uint32_t* r, uint32_t addr) {
    asm volatile("ldmatrix.sync.aligned.m8n8.x4.shared.b16 {%0,%1,%2,%3}, [%4];"
                 : "=r"(r[0]), "=r"(r[1]), "=r"(r[2]), "=r"(r[3]) : "r"(addr));
}
__device__ __forceinline__ void mma_fp16(float* d, const uint32_t* a,
                                         uint32_t b0, uint32_t b1) {
    asm volatile(
        "mma.sync.aligned.m16n8k16.row.col.f32.f16.f16.f32 "
        "{%0,%1,%2,%3}, {%4,%5,%6,%7}, {%8,%9}, {%0,%1,%2,%3};"
        : "+f"(d[0]), "+f"(d[1]), "+f"(d[2]), "+f"(d[3])
        : "r"(a[0]), "r"(a[1]), "r"(a[2]), "r"(a[3]), "r"(b0), "r"(b1));
}
__device__ __forceinline__ unsigned f2ord(float f) {
    unsigned raw = __float_as_uint(f);
    return (raw & 0x80000000u) ? ~raw : (raw | 0x80000000u);
}
__device__ __forceinline__ float ord2f(unsigned u) {
    return (u & 0x80000000u) ? __uint_as_float(u ^ 0x80000000u)
                             : __uint_as_float(~u);
}

// ---------------------------------------------------------------------------
// K1: prep_w — gate inline, A[d][s] = g1*We[e1][s][d] + g2*We[e2][s][d],
// fp16, K-major.  32x32 smem transpose tiles.  (Measured 5.9-6.2 us.)
// ---------------------------------------------------------------------------
__global__ void prep_w(const float* __restrict__ We,
                       const float* __restrict__ emb,
                       const float* __restrict__ Wg) {
    __shared__ float tile[32][33];
    __shared__ float s_g1, s_g2;
    __shared__ int s_e1, s_e2;

    int tx = threadIdx.x, ty = threadIdx.y;   // 32 x 8
    if (ty == 0) {
        int lane = tx;
        float t = -1e30f;
        if (lane < EE) {
            float s = 0.f;
            #pragma unroll
            for (int j = 0; j < EMBW; j++) s += emb[lane * EMBW + j] * Wg[DD + j];
            t = s;
        }
        float best = -1e30f, second = -1e30f;
        int be = 0, se = 0;
        #pragma unroll
        for (int e = 0; e < EE; e++) {
            float te = __shfl_sync(0xFFFFFFFFu, t, e);
            if (te > best)        { second = best; se = be; best = te; be = e; }
            else if (te > second) { second = te; se = e; }
        }
        if (lane == 0) {
            float e2 = expf(second - best);
            float inv = 1.0f / (1.0f + e2);
            s_g1 = inv;
            s_g2 = e2 * inv;
            s_e1 = be;
            s_e2 = se;
        }
    }
    __syncthreads();

    int s0 = blockIdx.x * 32, d0 = blockIdx.y * 32;
    float g1 = s_g1, g2 = s_g2;
    const float* A1 = We + (size_t)s_e1 * SS * DD;
    const float* A2 = We + (size_t)s_e2 * SS * DD;
    #pragma unroll
    for (int i = 0; i < 4; i++) {
        int s = s0 + ty + i * 8;
        tile[ty + i * 8][tx] =
            g1 * A1[(size_t)s * DD + d0 + tx] + g2 * A2[(size_t)s * DD + d0 + tx];
    }
    __syncthreads();
    #pragma unroll
    for (int i = 0; i < 4; i++) {
        int d = d0 + ty + i * 8;
        g_Ah[(size_t)d * SS + s0 + tx] = __float2half_rn(tile[tx][ty + i * 8]);
    }
}

// ---------------------------------------------------------------------------
// K2: prep_x — 2 channels per warp, LOCKSTEP dual 1-bit radix select
// (two independent REDUX chains per iteration overlap latencies), direct
// register write-back (no second smem pass).
// Block = (b, half of 32 channels): 256 thr / 8 warps, warp w owns local
// channels 2w, 2w+1.  1024 blocks, ~6 blocks/SM -> 1.15 waves (vs 1.73).
// ---------------------------------------------------------------------------
__global__ void __launch_bounds__(256) prep_x(const float* __restrict__ x) {
    __shared__ float sm[16 * 513];
    int b = blockIdx.x >> 1;
    int half = blockIdx.x & 1;
    const float4* xb4 = (const float4*)(x + (size_t)b * SS * CC + half * 16);

    for (int i = threadIdx.x; i < 512 * 4; i += 256) {
        int s = i >> 2, q = i & 3;
        float4 v = xb4[s * 8 + q];
        sm[(q * 4 + 0) * 513 + s] = v.x;
        sm[(q * 4 + 1) * 513 + s] = v.y;
        sm[(q * 4 + 2) * 513 + s] = v.z;
        sm[(q * 4 + 3) * 513 + s] = v.w;
    }
    __syncthreads();

    int w = threadIdx.x >> 5;
    int lane = threadIdx.x & 31;
    int c0 = 2 * w, c1 = 2 * w + 1;     // local channels

    unsigned u0[16], u1[16];
    #pragma unroll
    for (int r = 0; r < 16; r++) {
        u0[r] = f2ord(sm[c0 * 513 + lane + 32 * r]);
        u1[r] = f2ord(sm[c1 * 513 + lane + 32 * r]);
    }

    // lockstep dual 1-bit radix select (order stat 255, 0-indexed, each)
    unsigned act0 = 0xFFFFu, act1 = 0xFFFFu;
    int k0 = 255, na0 = 512;
    int k1 = 255, na1 = 512;
    for (int bit = 31; bit >= 0; bit--) {
        unsigned p0 = 0, p1 = 0;
        #pragma unroll
        for (int r = 0; r < 16; r++) {
            p0 |= ((((u0[r] >> bit) & 1u) ^ 1u) << r);
            p1 |= ((((u1[r] >> bit) & 1u) ^ 1u) << r);
        }
        p0 &= act0;
        p1 &= act1;
        int t0 = __reduce_add_sync(0xFFFFFFFFu, __popc(p0));
        int t1 = __reduce_add_sync(0xFFFFFFFFu, __popc(p1));
        if (na0 > 1) {
            if (k0 < t0) { act0 = p0; na0 = t0; }
            else         { k0 -= t0; act0 &= ~p0; na0 -= t0; }
        }
        if (na1 > 1) {
            if (k1 < t1) { act1 = p1; na1 = t1; }
            else         { k1 -= t1; act1 &= ~p1; na1 -= t1; }
        }
        if (na0 == 1 && na1 == 1) break;
    }

    // extract order stats 255 & 256 for both channels
    unsigned cand0 = 0, cand1 = 0;
    #pragma unroll
    for (int r = 0; r < 16; r++) {
        if ((act0 >> r) & 1u) cand0 = u0[r];
        if ((act1 >> r) & 1u) cand1 = u1[r];
    }
    unsigned v1a = __reduce_max_sync(0xFFFFFFFFu, cand0);
    unsigned v1b = __reduce_max_sync(0xFFFFFFFFu, cand1);

    int le0 = 0, le1 = 0;
    unsigned gt0 = 0xFFFFFFFFu, gt1 = 0xFFFFFFFFu;
    #pragma unroll
    for (int r = 0; r < 16; r++) {
        le0 += (u0[r] <= v1a) ? 1 : 0;
        le1 += (u1[r] <= v1b) ? 1 : 0;
        if (u0[r] > v1a && u0[r] < gt0) gt0 = u0[r];
        if (u1[r] > v1b && u1[r] < gt1) gt1 = u1[r];
    }
    int tle0 = __reduce_add_sync(0xFFFFFFFFu, le0);
    int tle1 = __reduce_add_sync(0xFFFFFFFFu, le1);
    unsigned mn0 = __reduce_min_sync(0xFFFFFFFFu, gt0);
    unsigned mn1 = __reduce_min_sync(0xFFFFFFFFu, gt1);
    unsigned v2a = (tle0 >= 257) ? v1a : mn0;
    unsigned v2b = (tle1 >= 257) ? v1b : mn1;
    float med0 = 0.5f * (ord2f(v1a) + ord2f(v2a));
    float med1 = 0.5f * (ord2f(v1b) + ord2f(v2b));

    // write xn = x - med as fp16 directly from register-resident values
    __half* dst0 = g_Xh + (size_t)(b * CC + half * 16 + c0) * SS;
    __half* dst1 = g_Xh + (size_t)(b * CC + half * 16 + c1) * SS;
    #pragma unroll
    for (int r = 0; r < 16; r++) {
        int s = lane + 32 * r;
        dst0[s] = __float2half_rn(ord2f(u0[r]) - med0);
        dst1[s] = __float2half_rn(ord2f(u1[r]) - med1);
    }
}

// ---------------------------------------------------------------------------
// K3: single-pass fp16 mma.sync GEMM — byte-exact R16 configuration
// (16 warps = 4/SMSP, warp tile 32x64, 4-stage prefetch-3 pipeline;
// measured total win).  CTA tile 128x256, grid 128, 192 KB smem.
// ---------------------------------------------------------------------------
#define CTA_M 128
#define CTA_N 256
#define KC 64
#define NCH (SS / KC)            // 8 chunks per n-tile
#define NTPC 2                   // n-tiles (of 256) per CTA
#define NIT (NTPC * NCH)         // 16 flat iterations
#define STG_BYTES 49152          // Ah 16K | Bh 32K
#define OFF_AH 0
#define OFF_BH 16384
#define NSTG 4
#define GSMEM (NSTG * STG_BYTES) // 196608

__global__ void __launch_bounds__(512) gemm_kernel(float* __restrict__ out) {
    extern __shared__ char smem[];
    uint32_t sb = smem_u32(smem);
    int tid = threadIdx.x;
    int lane = tid & 31, wid = tid >> 5;
    int wm = wid & 3;            // 4 m-groups of 32
    int wn = wid >> 2;           // 4 n-groups of 64
    int m0 = (blockIdx.x & 3) * CTA_M;
    int ng = blockIdx.x >> 2;    // n-group: 256-wide tiles ng*2 .. ng*2+1

    const char* gA = (const char*)(g_Ah + (size_t)m0 * SS);
    const char* gB = (const char*)g_Xh;

    auto ldchunk = [&](int stage, int it) {
        uint32_t tb = sb + stage * STG_BYTES;
        int u = it >> 3, ck = it & 7;
        size_t nrow0 = (size_t)(ng * NTPC + u) * CTA_N;
        size_t kb = (size_t)ck * (KC * 2);
        // A: 128 rows x 8 float4 = 1024
        #pragma unroll
        for (int t = 0; t < 2; t++) {
            int idx = tid + t * 512;
            int r = idx >> 3, c = idx & 7;
            uint32_t so = (uint32_t)(r * 128 + ((c * 16) ^ ((r & 7) << 4)));
            cp_async16(tb + OFF_AH + so,
                       gA + (size_t)r * (SS * 2) + kb + c * 16);
        }
        // B: 256 rows x 8 float4 = 2048
        #pragma unroll
        for (int t = 0; t < 4; t++) {
            int idx = tid + t * 512;
            int r = idx >> 3, c = idx & 7;
            uint32_t so = (uint32_t)(r * 128 + ((c * 16) ^ ((r & 7) << 4)));
            cp_async16(tb + OFF_BH + so,
                       gB + (nrow0 + r) * (SS * 2) + kb + c * 16);
        }
        asm volatile("cp.async.commit_group;" ::: "memory");
    };

    ldchunk(0, 0);
    ldchunk(1, 1);
    ldchunk(2, 2);

    float acc[2][8][4];
    int r8 = lane & 7;
    int half8 = ((lane >> 3) & 1) * 8;
    int kh16 = (lane >> 4) * 16;

    for (int it = 0; it < NIT; it++) {
        // group for 'it' complete; it+1, it+2 may remain outstanding
        asm volatile("cp.async.wait_group 2;" ::: "memory");
        __syncthreads();

        // stage (it+3)%4 == (it-1)%4 is free after the sync above
        if (it + 3 < NIT) ldchunk((it + 3) % NSTG, it + 3);
        else asm volatile("cp.async.commit_group;" ::: "memory");

        if ((it & 7) == 0) {
            #pragma unroll
            for (int i = 0; i < 2; i++)
                #pragma unroll
                for (int j = 0; j < 8; j++)
                    #pragma unroll
                    for (int q = 0; q < 4; q++) acc[i][j][q] = 0.f;
        }

        uint32_t tb = sb + (it % NSTG) * STG_BYTES;
        #pragma unroll
        for (int ks = 0; ks < 4; ks++) {
            int kb0 = ks * 32 + kh16;
            uint32_t a[2][4], bfr[4][4];
            #pragma unroll
            for (int mb = 0; mb < 2; mb++) {
                int row = wm * 32 + mb * 16 + half8 + r8;
                uint32_t ad = (uint32_t)(row * 128 + (kb0 ^ ((row & 7) << 4)));
                ldsm4(a[mb], tb + OFF_AH + ad);
            }
            #pragma unroll
            for (int nb2 = 0; nb2 < 4; nb2++) {
                int row = wn * 64 + nb2 * 16 + half8 + r8;
                uint32_t ad = (uint32_t)(row * 128 + (kb0 ^ ((row & 7) << 4)));
                ldsm4(bfr[nb2], tb + OFF_BH + ad);
            }
            #pragma unroll
            for (int mb = 0; mb < 2; mb++)
                #pragma unroll
                for (int nb2 = 0; nb2 < 4; nb2++)
                    #pragma unroll
                    for (int s = 0; s < 2; s++)
                        mma_fp16(acc[mb][nb2 * 2 + s], a[mb],
                                 bfr[nb2][s], bfr[nb2][s + 2]);
        }

        if ((it & 7) == 7) {
            // store n-tile: warp covers n in [wn*64, wn*64+64) = 2 batch rows
            int u = it >> 3;
            int nbase = (ng * NTPC + u) * CTA_N + wn * 64;
            #pragma unroll
            for (int mb = 0; mb < 2; mb++) {
                int dr = m0 + wm * 32 + mb * 16 + (lane >> 2);
                #pragma unroll
                for (int nb8 = 0; nb8 < 8; nb8++) {
                    int bidx = (nbase >> 5) + (nb8 >> 2);
                    int v = (nb8 & 3) * 8 + 2 * (lane & 3);
                    float* ob = out + (size_t)bidx * DD * CC;
                    *(float2*)(ob + (size_t)dr * CC + v) =
                        make_float2(acc[mb][nb8][0], acc[mb][nb8][1]);
                    *(float2*)(ob + (size_t)(dr + 8) * CC + v) =
                        make_float2(acc[mb][nb8][2], acc[mb][nb8][3]);
                }
            }
        }
    }
}

// ---------------------------------------------------------------------------
// Launch.  Inputs: x, Wp, bp, emb, Wg, bg, We, k  (Wp/bp/bg/k provably unused)
// ---------------------------------------------------------------------------
extern "C" void kernel_launch(void* const* d_in, const int* in_sizes, int n_in,
                              void* d_out, int out_size) {
    const float* x   = (const float*)d_in[0];
    const float* emb = (const float*)d_in[3];
    const float* Wg  = (const float*)d_in[4];
    const float* We  = (const float*)d_in[6];
    float* out = (float*)d_out;

    cudaFuncSetAttribute(gemm_kernel,
                         cudaFuncAttributeMaxDynamicSharedMemorySize, GSMEM);

    prep_w<<<dim3(16, 16), dim3(32, 8)>>>(We, emb, Wg);
    prep_x<<<BB * 2, 256>>>(x);
    gemm_kernel<<<128, 512, GSMEM>>>(out);
}